// round 9
// baseline (speedup 1.0000x reference)
#include <cuda_runtime.h>
#include <cuda_bf16.h>

// ROI-Align (Mask R-CNN multi-level crop_and_resize), POOL=7, C=256, N=1000.
// R6: R4 data path (register corner offsets/weights, 4 LDG + FMA + STG, unroll 4,
// grid=1000 — the config measured at DRAM=14%), with __launch_bounds__(196,7)
// so all 1000 blocks are resident in a single wave (148 SMs x 7 = 1036): no tail
// wave, ~43 warps/SM for latency hiding.

#define POOLP 49
#define CCH   256
#define NGRP  4                 // channel groups per box
#define CPG   (CCH / NGRP)      // 64 channels per thread
#define NTHR  (POOLP * NGRP)    // 196 threads

__global__ __launch_bounds__(NTHR, 7) void roialign_kernel(
    const float* __restrict__ boxes,
    const float* __restrict__ p2,
    const float* __restrict__ p3,
    const float* __restrict__ p4,
    const float* __restrict__ p5,
    float* __restrict__ out)
{
    const int n = blockIdx.x;
    const int tid = threadIdx.x;
    const int pos = tid % POOLP;
    const int grp = tid / POOLP;        // 0..3
    const int py = pos / 7;
    const int px = pos - py * 7;

    const float y1 = __ldg(boxes + n * 4 + 0);
    const float x1 = __ldg(boxes + n * 4 + 1);
    const float y2 = __ldg(boxes + n * 4 + 2);
    const float x2 = __ldg(boxes + n * 4 + 3);

    // roi_level = clip(round(4 + log2(sqrt(h*w) / (224/1024))), 2, 5); round half-to-even.
    const float lvl_f = 4.0f + log2f(sqrtf((y2 - y1) * (x2 - x1)) / 0.21875f);
    int lvl = (int)rintf(lvl_f);
    lvl = lvl < 2 ? 2 : (lvl > 5 ? 5 : lvl);

    const float* fm;
    int H;
    if      (lvl == 2) { fm = p2; H = 256; }
    else if (lvl == 3) { fm = p3; H = 128; }
    else if (lvl == 4) { fm = p4; H = 64;  }
    else               { fm = p5; H = 32;  }
    const int W  = H;
    const int HW = H * W;

    // Sample coordinates; match jax f32 arithmetic (t = i / 6.0f as division).
    const float ty = (float)py / 6.0f;
    const float tx = (float)px / 6.0f;
    const float yy = (y1 + (y2 - y1) * ty) * (float)(H - 1);
    const float xx = (x1 + (x2 - x1) * tx) * (float)(W - 1);

    const float y0f = floorf(yy);
    const float x0f = floorf(xx);
    const float wy = yy - y0f;
    const float wx = xx - x0f;

    int iy0 = (int)y0f; iy0 = iy0 < 0 ? 0 : (iy0 > H - 1 ? H - 1 : iy0);
    int iy1 = (iy0 + 1 > H - 1) ? (H - 1) : (iy0 + 1);
    int ix0 = (int)x0f; ix0 = ix0 < 0 ? 0 : (ix0 > W - 1 ? W - 1 : ix0);
    int ix1 = (ix0 + 1 > W - 1) ? (W - 1) : (ix0 + 1);

    const bool inb = (yy >= 0.0f) && (yy <= (float)(H - 1)) &&
                     (xx >= 0.0f) && (xx <= (float)(W - 1));
    const float m = inb ? 1.0f : 0.0f;

    // Register-resident offsets and weights for this thread's fixed pos.
    const int o00 = iy0 * W + ix0;
    const int o01 = iy0 * W + ix1;
    const int o10 = iy1 * W + ix0;
    const int o11 = iy1 * W + ix1;
    const float w00 = m * (1.0f - wy) * (1.0f - wx);
    const float w01 = m * (1.0f - wy) * wx;
    const float w10 = m * wy * (1.0f - wx);
    const float w11 = m * wy * wx;

    const float* __restrict__ b  = fm + (size_t)(grp * CPG) * HW;
    float*       __restrict__ po = out + (size_t)n * (CCH * POOLP)
                                       + (size_t)(grp * CPG) * POOLP + pos;

    #pragma unroll 4
    for (int c = 0; c < CPG; ++c) {
        float v = w00 * __ldg(b + o00)
                + w01 * __ldg(b + o01)
                + w10 * __ldg(b + o10)
                + w11 * __ldg(b + o11);
        *po = v;
        b  += HW;
        po += POOLP;
    }
}

extern "C" void kernel_launch(void* const* d_in, const int* in_sizes, int n_in,
                              void* d_out, int out_size)
{
    const float* boxes = (const float*)d_in[0];
    const float* p2    = (const float*)d_in[1];
    const float* p3    = (const float*)d_in[2];
    const float* p4    = (const float*)d_in[3];
    const float* p5    = (const float*)d_in[4];
    float* out = (float*)d_out;

    roialign_kernel<<<1000, NTHR>>>(boxes, p2, p3, p4, p5, out);
}

// round 12
// speedup vs baseline: 1.3672x; 1.3672x over previous
#include <cuda_runtime.h>
#include <cuda_bf16.h>

// ROI-Align (Mask R-CNN multi-level crop_and_resize), POOL=7, C=256, N=1000.
// R7: level/channel-major restructure. Hot kernel block = (channel, level):
// all gathers of that block come from ONE feature plane -> L1-resident gathers
// (39cyc) instead of L2 hits (~240cyc). Per-sample bilinear params precomputed
// once (not per channel) into __device__ scratch.

#define NBOX  1000
#define POOLP 49
#define CCH   256
#define MAXS  (NBOX * POOLP)

__device__ int    g_count[4];
__device__ int    g_list[4][NBOX];
__device__ int4   g_off[4][MAXS];    // 4 clamped in-plane offsets
__device__ float4 g_wgt[4][MAXS];    // 4 bilinear weights (mask folded in)
__device__ int    g_ob [4][MAXS];    // n*12544 + pos  (output base sans channel)

// -- reset counters --------------------------------------------------------
__global__ void kZ() {
    if (threadIdx.x < 4) g_count[threadIdx.x] = 0;
}

// -- per-box level + compaction -------------------------------------------
__global__ void kA(const float* __restrict__ boxes) {
    int n = blockIdx.x * blockDim.x + threadIdx.x;
    if (n >= NBOX) return;
    float y1 = boxes[n * 4 + 0];
    float x1 = boxes[n * 4 + 1];
    float y2 = boxes[n * 4 + 2];
    float x2 = boxes[n * 4 + 3];
    // roi_level = clip(round(4 + log2(sqrt(h*w)/0.21875)), 2, 5); round half-to-even.
    float lvl_f = 4.0f + log2f(sqrtf((y2 - y1) * (x2 - x1)) / 0.21875f);
    int lvl = (int)rintf(lvl_f);
    lvl = lvl < 2 ? 2 : (lvl > 5 ? 5 : lvl);
    int l = lvl - 2;
    int slot = atomicAdd(&g_count[l], 1);
    g_list[l][slot] = n;
}

// -- per-sample bilinear params (once, channel-independent) ----------------
__global__ void kB(const float* __restrict__ boxes) {
    const int l = blockIdx.y;                       // 0..3 -> levels 2..5
    const int s = blockIdx.x * blockDim.x + threadIdx.x;
    const int ns = g_count[l] * POOLP;
    if (s >= ns) return;

    const int bslot = s / POOLP;
    const int pos   = s - bslot * POOLP;
    const int n     = g_list[l][bslot];
    const int py = pos / 7;
    const int px = pos - py * 7;

    const int H = 256 >> l;
    const int W = H;

    const float y1 = boxes[n * 4 + 0];
    const float x1 = boxes[n * 4 + 1];
    const float y2 = boxes[n * 4 + 2];
    const float x2 = boxes[n * 4 + 3];

    // Match jax f32 arithmetic (t = i / 6.0f as division).
    const float ty = (float)py / 6.0f;
    const float tx = (float)px / 6.0f;
    const float yy = (y1 + (y2 - y1) * ty) * (float)(H - 1);
    const float xx = (x1 + (x2 - x1) * tx) * (float)(W - 1);

    const float y0f = floorf(yy);
    const float x0f = floorf(xx);
    const float wy = yy - y0f;
    const float wx = xx - x0f;

    int iy0 = (int)y0f; iy0 = iy0 < 0 ? 0 : (iy0 > H - 1 ? H - 1 : iy0);
    int iy1 = (iy0 + 1 > H - 1) ? (H - 1) : (iy0 + 1);
    int ix0 = (int)x0f; ix0 = ix0 < 0 ? 0 : (ix0 > W - 1 ? W - 1 : ix0);
    int ix1 = (ix0 + 1 > W - 1) ? (W - 1) : (ix0 + 1);

    const bool inb = (yy >= 0.0f) && (yy <= (float)(H - 1)) &&
                     (xx >= 0.0f) && (xx <= (float)(W - 1));
    const float m = inb ? 1.0f : 0.0f;

    int4 o;
    o.x = iy0 * W + ix0;
    o.y = iy0 * W + ix1;
    o.z = iy1 * W + ix0;
    o.w = iy1 * W + ix1;
    float4 w;
    w.x = m * (1.0f - wy) * (1.0f - wx);
    w.y = m * (1.0f - wy) * wx;
    w.z = m * wy * (1.0f - wx);
    w.w = m * wy * wx;

    g_off[l][s] = o;
    g_wgt[l][s] = w;
    g_ob [l][s] = n * (CCH * POOLP) + pos;
}

// -- hot kernel: one (channel, level) plane per block ----------------------
__global__ __launch_bounds__(256) void k2(
    const float* __restrict__ p2,
    const float* __restrict__ p3,
    const float* __restrict__ p4,
    const float* __restrict__ p5,
    float* __restrict__ out)
{
    const int c = blockIdx.x;       // 0..255
    const int l = blockIdx.y;       // 0..3
    const int ns = g_count[l] * POOLP;
    if (ns == 0) return;

    const float* fm;
    int H;
    if      (l == 0) { fm = p2; H = 256; }
    else if (l == 1) { fm = p3; H = 128; }
    else if (l == 2) { fm = p4; H = 64;  }
    else             { fm = p5; H = 32;  }
    const int HW = H * H;

    const float* __restrict__ pl = fm + (size_t)c * HW;
    const int4*   __restrict__ off = g_off[l];
    const float4* __restrict__ wgt = g_wgt[l];
    const int*    __restrict__ ob  = g_ob[l];
    const int cofs = c * POOLP;

    #pragma unroll 2
    for (int j = threadIdx.x; j < ns; j += 256) {
        const int4   o = off[j];
        const float4 w = wgt[j];
        float v = w.x * __ldg(pl + o.x)
                + w.y * __ldg(pl + o.y)
                + w.z * __ldg(pl + o.z)
                + w.w * __ldg(pl + o.w);
        out[ob[j] + cofs] = v;
    }
}

extern "C" void kernel_launch(void* const* d_in, const int* in_sizes, int n_in,
                              void* d_out, int out_size)
{
    const float* boxes = (const float*)d_in[0];
    const float* p2    = (const float*)d_in[1];
    const float* p3    = (const float*)d_in[2];
    const float* p4    = (const float*)d_in[3];
    const float* p5    = (const float*)d_in[4];
    float* out = (float*)d_out;

    kZ<<<1, 32>>>();
    kA<<<(NBOX + 255) / 256, 256>>>(boxes);
    kB<<<dim3((MAXS + 255) / 256, 4), 256>>>(boxes);
    k2<<<dim3(CCH, 4), 256>>>(p2, p3, p4, p5, out);
}

// round 13
// speedup vs baseline: 1.6116x; 1.1788x over previous
#include <cuda_runtime.h>
#include <cuda_bf16.h>

// ROI-Align (Mask R-CNN multi-level crop_and_resize), POOL=7, C=256, N=1000.
// R8: level/channel-major. Hot kernel: block = (channel-group of 4, level, chunk).
// Per-sample bilinear params loaded ONCE per 4 channels (param traffic /4), and
// the 16 gathers per param load are independent -> high MLP to cover L1/L2 latency.

#define NBOX  1000
#define POOLP 49
#define CCH   256
#define MAXS  (NBOX * POOLP)
#define CPT   4                  // channels per thread in hot kernel
#define NCG   (CCH / CPT)        // 64 channel groups
#define CHUNKS 6

__device__ int    g_count[4];
__device__ int    g_list[4][NBOX];
__device__ int4   g_off[4][MAXS];    // 4 clamped in-plane offsets
__device__ float4 g_wgt[4][MAXS];    // 4 bilinear weights (mask folded in)
__device__ int    g_ob [4][MAXS];    // n*12544 + pos (output base sans channel)

// -- fused: zero counters + per-box level + compaction (single block) ------
__global__ __launch_bounds__(1024) void kZA(const float* __restrict__ boxes) {
    __shared__ int s_cnt[4];
    if (threadIdx.x < 4) s_cnt[threadIdx.x] = 0;
    __syncthreads();

    const int n = threadIdx.x;
    int l = -1, slot = 0;
    if (n < NBOX) {
        float y1 = boxes[n * 4 + 0];
        float x1 = boxes[n * 4 + 1];
        float y2 = boxes[n * 4 + 2];
        float x2 = boxes[n * 4 + 3];
        // roi_level = clip(round(4 + log2(sqrt(h*w)/0.21875)), 2, 5); round half-to-even.
        float lvl_f = 4.0f + log2f(sqrtf((y2 - y1) * (x2 - x1)) / 0.21875f);
        int lvl = (int)rintf(lvl_f);
        lvl = lvl < 2 ? 2 : (lvl > 5 ? 5 : lvl);
        l = lvl - 2;
        slot = atomicAdd(&s_cnt[l], 1);
        g_list[l][slot] = n;
    }
    __syncthreads();
    if (threadIdx.x < 4) g_count[threadIdx.x] = s_cnt[threadIdx.x];
}

// -- per-sample bilinear params (channel-independent, computed once) -------
__global__ void kB(const float* __restrict__ boxes) {
    const int l = blockIdx.y;                       // 0..3 -> levels 2..5
    const int s = blockIdx.x * blockDim.x + threadIdx.x;
    const int ns = g_count[l] * POOLP;
    if (s >= ns) return;

    const int bslot = s / POOLP;
    const int pos   = s - bslot * POOLP;
    const int n     = g_list[l][bslot];
    const int py = pos / 7;
    const int px = pos - py * 7;

    const int H = 256 >> l;
    const int W = H;

    const float y1 = boxes[n * 4 + 0];
    const float x1 = boxes[n * 4 + 1];
    const float y2 = boxes[n * 4 + 2];
    const float x2 = boxes[n * 4 + 3];

    // Match jax f32 arithmetic (t = i / 6.0f as division).
    const float ty = (float)py / 6.0f;
    const float tx = (float)px / 6.0f;
    const float yy = (y1 + (y2 - y1) * ty) * (float)(H - 1);
    const float xx = (x1 + (x2 - x1) * tx) * (float)(W - 1);

    const float y0f = floorf(yy);
    const float x0f = floorf(xx);
    const float wy = yy - y0f;
    const float wx = xx - x0f;

    int iy0 = (int)y0f; iy0 = iy0 < 0 ? 0 : (iy0 > H - 1 ? H - 1 : iy0);
    int iy1 = (iy0 + 1 > H - 1) ? (H - 1) : (iy0 + 1);
    int ix0 = (int)x0f; ix0 = ix0 < 0 ? 0 : (ix0 > W - 1 ? W - 1 : ix0);
    int ix1 = (ix0 + 1 > W - 1) ? (W - 1) : (ix0 + 1);

    const bool inb = (yy >= 0.0f) && (yy <= (float)(H - 1)) &&
                     (xx >= 0.0f) && (xx <= (float)(W - 1));
    const float m = inb ? 1.0f : 0.0f;

    int4 o;
    o.x = iy0 * W + ix0;
    o.y = iy0 * W + ix1;
    o.z = iy1 * W + ix0;
    o.w = iy1 * W + ix1;
    float4 w;
    w.x = m * (1.0f - wy) * (1.0f - wx);
    w.y = m * (1.0f - wy) * wx;
    w.z = m * wy * (1.0f - wx);
    w.w = m * wy * wx;

    g_off[l][s] = o;
    g_wgt[l][s] = w;
    g_ob [l][s] = n * (CCH * POOLP) + pos;
}

// -- hot kernel: (channel-group of 4, level, chunk) per block --------------
__global__ __launch_bounds__(256) void k2(
    const float* __restrict__ p2,
    const float* __restrict__ p3,
    const float* __restrict__ p4,
    const float* __restrict__ p5,
    float* __restrict__ out)
{
    const int cg    = blockIdx.x;   // 0..63
    const int l     = blockIdx.y;   // 0..3
    const int chunk = blockIdx.z;   // 0..CHUNKS-1
    const int ns = g_count[l] * POOLP;

    const int j0 = chunk * 256 + threadIdx.x;
    if (j0 >= ns) return;

    const float* fm;
    int H;
    if      (l == 0) { fm = p2; H = 256; }
    else if (l == 1) { fm = p3; H = 128; }
    else if (l == 2) { fm = p4; H = 64;  }
    else             { fm = p5; H = 32;  }
    const int HW = H * H;

    const int c0 = cg * CPT;
    const float* __restrict__ pl0 = fm + (size_t)(c0 + 0) * HW;
    const float* __restrict__ pl1 = fm + (size_t)(c0 + 1) * HW;
    const float* __restrict__ pl2 = fm + (size_t)(c0 + 2) * HW;
    const float* __restrict__ pl3 = fm + (size_t)(c0 + 3) * HW;

    const int4*   __restrict__ off = g_off[l];
    const float4* __restrict__ wgt = g_wgt[l];
    const int*    __restrict__ obp = g_ob[l];

    #pragma unroll 2
    for (int j = j0; j < ns; j += 256 * CHUNKS) {
        const int4   o = __ldg(off + j);
        const float4 w = __ldg(wgt + j);
        const int   ob = __ldg(obp + j);

        float v0 = w.x * __ldg(pl0 + o.x) + w.y * __ldg(pl0 + o.y)
                 + w.z * __ldg(pl0 + o.z) + w.w * __ldg(pl0 + o.w);
        float v1 = w.x * __ldg(pl1 + o.x) + w.y * __ldg(pl1 + o.y)
                 + w.z * __ldg(pl1 + o.z) + w.w * __ldg(pl1 + o.w);
        float v2 = w.x * __ldg(pl2 + o.x) + w.y * __ldg(pl2 + o.y)
                 + w.z * __ldg(pl2 + o.z) + w.w * __ldg(pl2 + o.w);
        float v3 = w.x * __ldg(pl3 + o.x) + w.y * __ldg(pl3 + o.y)
                 + w.z * __ldg(pl3 + o.z) + w.w * __ldg(pl3 + o.w);

        out[ob + (c0 + 0) * POOLP] = v0;
        out[ob + (c0 + 1) * POOLP] = v1;
        out[ob + (c0 + 2) * POOLP] = v2;
        out[ob + (c0 + 3) * POOLP] = v3;
    }
}

extern "C" void kernel_launch(void* const* d_in, const int* in_sizes, int n_in,
                              void* d_out, int out_size)
{
    const float* boxes = (const float*)d_in[0];
    const float* p2    = (const float*)d_in[1];
    const float* p3    = (const float*)d_in[2];
    const float* p4    = (const float*)d_in[3];
    const float* p5    = (const float*)d_in[4];
    float* out = (float*)d_out;

    kZA<<<1, 1024>>>(boxes);
    kB<<<dim3((MAXS + 255) / 256, 4), 256>>>(boxes);
    k2<<<dim3(NCG, 4, CHUNKS), 256>>>(p2, p3, p4, p5, out);
}